// round 1
// baseline (speedup 1.0000x reference)
#include <cuda_runtime.h>

// ---------------------------------------------------------------------------
// BaseLoftqLinear: out[b,s,o] = sum_k x[b,s,k] * W[o,k] + bias[o]
//                             + 2.0 * sum_r (sum_k x*A[r,k]) * B[o,r]
// where W = dequant4bit(qweight, scales), table = linspace(-1,1,16),
// per-64-element block scaling over the flattened [OUT_F*IN_F] weight.
//
// Strategy: fold LoRA into the weights:  W' = W + 2.0 * (B @ A)  [4096x4096]
// then a single fp32 SGEMM: out = x @ W'^T + bias.
// ---------------------------------------------------------------------------

#define OUT_F 4096
#define IN_F  4096
#define M_TOK 2048          // 2 * 1024
#define R_LORA 16
#define LORA_SCALE 2.0f     // 32.0 / 16

// 64 MB device scratch for the merged dequantized weight (allowed: static
// __device__ array, no runtime allocation).
__device__ float g_W[(size_t)OUT_F * IN_F];

// ---------------------------------------------------------------------------
// Kernel 1: dequant + LoRA fold.
// qweight: int32 array, one byte-value (0..255) per element; element i holds
// flat weight indices 2i (low nibble) and 2i+1 (high nibble).
// flat index f -> o = f / IN_F, k = f % IN_F, scale block = f / 64.
// ---------------------------------------------------------------------------
__global__ __launch_bounds__(256)
void dequant_lora_kernel(const int* __restrict__ qweight,
                         const float* __restrict__ scales,
                         const float* __restrict__ lora_A,   // [R, IN_F]
                         const float* __restrict__ lora_B)   // [OUT_F, R]
{
    int i = blockIdx.x * blockDim.x + threadIdx.x;       // 0 .. OUT_F*IN_F/2-1
    const int total = OUT_F * IN_F / 2;
    if (i >= total) return;

    int q = qweight[i];
    int f0 = 2 * i;                 // even flat index
    // both nibbles fall in the same 64-element scale block
    float s = scales[f0 >> 6];

    const float step = 2.0f / 15.0f;
    float v0 = fmaf((float)(q & 15),        step, -1.0f) * s;
    float v1 = fmaf((float)((q >> 4) & 15), step, -1.0f) * s;

    int o  = f0 >> 12;              // f0 / 4096
    int k0 = f0 & 4095;             // even, so k0+1 is in the same row

    float l0 = 0.0f, l1 = 0.0f;
#pragma unroll
    for (int r = 0; r < R_LORA; r++) {
        float b = lora_B[o * R_LORA + r];
        l0 = fmaf(b, lora_A[r * IN_F + k0],     l0);
        l1 = fmaf(b, lora_A[r * IN_F + k0 + 1], l1);
    }

    g_W[f0]     = fmaf(LORA_SCALE, l0, v0);
    g_W[f0 + 1] = fmaf(LORA_SCALE, l1, v1);
}

// ---------------------------------------------------------------------------
// Kernel 2: SGEMM  out[M, N] = x[M, K] @ W'[N, K]^T + bias[N]
// 128x128 block tile, BK=8, 256 threads, 8x8 per-thread microtile.
// ---------------------------------------------------------------------------
#define BM 128
#define BN 128
#define BK 8
#define TM 8
#define TN 8

__global__ __launch_bounds__(256)
void sgemm_bias_kernel(const float* __restrict__ x,
                       const float* __restrict__ bias,
                       float* __restrict__ out)
{
    __shared__ float As[BK][BM];   // transposed: As[k][m]
    __shared__ float Bs[BK][BN];   // transposed: Bs[k][n]

    const int bm = blockIdx.y * BM;
    const int bn = blockIdx.x * BN;
    const int t  = threadIdx.x;
    const int tx = t & 15;          // 0..15  (N direction)
    const int ty = t >> 4;          // 0..15  (M direction)

    // global-load mapping: 128 rows x 8 cols per tile; 2 threads per row,
    // each loads one float4.
    const int lrow = t >> 1;        // 0..127
    const int lcol = (t & 1) * 4;   // 0 or 4

    const float* xg = x   + (size_t)(bm + lrow) * IN_F + lcol;
    const float* wg = g_W + (size_t)(bn + lrow) * IN_F + lcol;

    float acc[TM][TN];
#pragma unroll
    for (int i = 0; i < TM; i++)
#pragma unroll
        for (int j = 0; j < TN; j++) acc[i][j] = 0.0f;

    // prefetch first tile
    float4 av = *(const float4*)(xg);
    float4 bv = *(const float4*)(wg);

    for (int kt = 0; kt < IN_F; kt += BK) {
        // stage current tile into shared (transposed)
        As[lcol + 0][lrow] = av.x;
        As[lcol + 1][lrow] = av.y;
        As[lcol + 2][lrow] = av.z;
        As[lcol + 3][lrow] = av.w;
        Bs[lcol + 0][lrow] = bv.x;
        Bs[lcol + 1][lrow] = bv.y;
        Bs[lcol + 2][lrow] = bv.z;
        Bs[lcol + 3][lrow] = bv.w;
        __syncthreads();

        // issue next tile's global loads early (hide LDG under compute)
        if (kt + BK < IN_F) {
            av = *(const float4*)(xg + kt + BK);
            bv = *(const float4*)(wg + kt + BK);
        }

#pragma unroll
        for (int kk = 0; kk < BK; kk++) {
            float a[TM], b[TN];
            // vector-friendly fragment loads (16B aligned)
            *(float4*)&a[0] = *(const float4*)&As[kk][ty * TM];
            *(float4*)&a[4] = *(const float4*)&As[kk][ty * TM + 4];
            *(float4*)&b[0] = *(const float4*)&Bs[kk][tx * TN];
            *(float4*)&b[4] = *(const float4*)&Bs[kk][tx * TN + 4];
#pragma unroll
            for (int i = 0; i < TM; i++)
#pragma unroll
                for (int j = 0; j < TN; j++)
                    acc[i][j] = fmaf(a[i], b[j], acc[i][j]);
        }
        __syncthreads();
    }

    // epilogue: add bias, store
#pragma unroll
    for (int i = 0; i < TM; i++) {
        const int m = bm + ty * TM + i;
        float* op = out + (size_t)m * OUT_F + bn + tx * TN;
        const float* bp = bias + bn + tx * TN;
#pragma unroll
        for (int j = 0; j < TN; j += 4) {
            float4 bb = *(const float4*)(bp + j);
            float4 vv;
            vv.x = acc[i][j + 0] + bb.x;
            vv.y = acc[i][j + 1] + bb.y;
            vv.z = acc[i][j + 2] + bb.z;
            vv.w = acc[i][j + 3] + bb.w;
            *(float4*)(op + j) = vv;
        }
    }
}

// ---------------------------------------------------------------------------
// Launch
// inputs (metadata order): x, qweight, scales, bias, lora_A, lora_B
// ---------------------------------------------------------------------------
extern "C" void kernel_launch(void* const* d_in, const int* in_sizes, int n_in,
                              void* d_out, int out_size)
{
    const float* x      = (const float*)d_in[0];
    const int*   qw     = (const int*)  d_in[1];
    const float* scales = (const float*)d_in[2];
    const float* bias   = (const float*)d_in[3];
    const float* lora_A = (const float*)d_in[4];
    const float* lora_B = (const float*)d_in[5];
    float*       out    = (float*)d_out;

    (void)in_sizes; (void)n_in; (void)out_size;

    // 1) dequant + LoRA fold into g_W
    const int half_elems = OUT_F * IN_F / 2;       // 8,388,608
    dequant_lora_kernel<<<(half_elems + 255) / 256, 256>>>(qw, scales, lora_A, lora_B);

    // 2) GEMM + bias
    dim3 grid(OUT_F / BN, M_TOK / BM);             // (32, 16)
    sgemm_bias_kernel<<<grid, 256>>>(x, bias, out);
}

// round 3
// speedup vs baseline: 3.2275x; 3.2275x over previous
#include <cuda_runtime.h>
#include <cstdint>

// ---------------------------------------------------------------------------
// BaseLoftqLinear:
//   W' = dequant4(q, s) + 2.0 * (B @ A)      (LoRA folded into weights)
//   out = x @ W'^T + bias
// GEMM via mma.sync tf32 (non-'a' PTX feature set; tcgen05 unavailable because
// the harness PTX targets plain sm_103).
// ---------------------------------------------------------------------------

#define OUT_F 4096
#define IN_F  4096
#define M_TOK 2048
#define R_LORA 16

__device__ float g_W[(size_t)OUT_F * IN_F];   // tf32-rounded merged weights
__device__ float g_X[(size_t)M_TOK * IN_F];   // tf32-rounded activations

__device__ __forceinline__ float tf32_rna(float v) {
    uint32_t r;
    asm("cvt.rna.tf32.f32 %0, %1;" : "=r"(r) : "f"(v));
    return __uint_as_float(r);
}

__device__ __forceinline__ uint32_t smem_u32(const void* p) {
    uint32_t a;
    asm("{ .reg .u64 t; cvta.to.shared.u64 t, %1; cvt.u32.u64 %0, t; }"
        : "=r"(a) : "l"(p));
    return a;
}

// ---------------------------------------------------------------------------
// Kernel 1: dequant + LoRA fold -> tf32-rounded fp32 W'
// ---------------------------------------------------------------------------
__global__ __launch_bounds__(256)
void dequant_lora_kernel(const int* __restrict__ qweight,
                         const float* __restrict__ scales,
                         const float* __restrict__ lora_A,   // [R, IN_F]
                         const float* __restrict__ lora_B)   // [OUT_F, R]
{
    int i = blockIdx.x * 256 + threadIdx.x;         // 0 .. OUT_F*IN_F/2-1
    int q = qweight[i];
    int f0 = 2 * i;
    float s = scales[f0 >> 6];

    const float step = 2.0f / 15.0f;
    float v0 = fmaf((float)(q & 15),        step, -1.0f) * s;
    float v1 = fmaf((float)((q >> 4) & 15), step, -1.0f) * s;

    int o  = f0 >> 12;
    int k0 = f0 & 4095;

    float l0 = 0.0f, l1 = 0.0f;
#pragma unroll
    for (int r = 0; r < R_LORA; r++) {
        float b = lora_B[o * R_LORA + r];
        l0 = fmaf(b, lora_A[r * IN_F + k0],     l0);
        l1 = fmaf(b, lora_A[r * IN_F + k0 + 1], l1);
    }
    g_W[f0]     = tf32_rna(fmaf(2.0f, l0, v0));
    g_W[f0 + 1] = tf32_rna(fmaf(2.0f, l1, v1));
}

// ---------------------------------------------------------------------------
// Kernel 2: tf32-round x
// ---------------------------------------------------------------------------
__global__ __launch_bounds__(256)
void convert_x_kernel(const float* __restrict__ x)
{
    int i = (blockIdx.x * 256 + threadIdx.x) * 4;
    float4 v = *(const float4*)(x + i);
    float4 r;
    r.x = tf32_rna(v.x); r.y = tf32_rna(v.y);
    r.z = tf32_rna(v.z); r.w = tf32_rna(v.w);
    *(float4*)(g_X + i) = r;
}

// ---------------------------------------------------------------------------
// Kernel 3: tf32 tensor-core GEMM  out[M,N] = X @ W'^T + bias
// CTA 128x128, BK=32, 3-stage cp.async pipeline, 8 warps (2M x 4N),
// warp tile 64x32, mma.sync.m16n8k8.
// ---------------------------------------------------------------------------
#define BM 128
#define BN 128
#define BK 32
#define NITER (IN_F / BK)          // 128
#define STAGES 3
#define ASTRIDE 36                 // floats per smem row (pad: conflict-free frags)
#define TILE_FLOATS (128 * ASTRIDE)
#define SMEM_BYTES (2 * STAGES * TILE_FLOATS * 4)   // 110592

__device__ __forceinline__ void cp_async16(uint32_t dst, const float* src) {
    asm volatile("cp.async.cg.shared.global [%0], [%1], 16;"
                 :: "r"(dst), "l"(src) : "memory");
}

__device__ __forceinline__ void mma_tf32(float* d, const uint32_t* a, const uint32_t* b) {
    asm volatile(
        "mma.sync.aligned.m16n8k8.row.col.f32.tf32.tf32.f32 "
        "{%0,%1,%2,%3}, {%4,%5,%6,%7}, {%8,%9}, {%0,%1,%2,%3};"
        : "+f"(d[0]), "+f"(d[1]), "+f"(d[2]), "+f"(d[3])
        : "r"(a[0]), "r"(a[1]), "r"(a[2]), "r"(a[3]),
          "r"(b[0]), "r"(b[1]));
}

__global__ __launch_bounds__(256, 2)
void gemm_tf32_kernel(const float* __restrict__ bias, float* __restrict__ out)
{
    extern __shared__ float smem[];
    float* As = smem;                            // [STAGES][128][ASTRIDE]
    float* Bs = smem + STAGES * TILE_FLOATS;

    const int t    = threadIdx.x;
    const int lane = t & 31;
    const int wid  = t >> 5;
    const int g4   = lane >> 2;                  // 0..7
    const int l4   = lane & 3;                   // 0..3
    const int wm   = wid & 1;                    // M-warp (0..1)
    const int wn   = wid >> 1;                   // N-warp (0..3)

    const float* gA = g_X + (size_t)(blockIdx.y * BM) * IN_F;
    const float* gB = g_W + (size_t)(blockIdx.x * BN) * IN_F;

    // per-thread load slots: id = t + i*256; row = id>>3 (0..127), chunk = id&7
    const int lrow = t >> 3;          // base row for i=0 (+32 per i)
    const int lch  = t & 7;           // 16B chunk within 128B row

    float acc[4][4][4];
#pragma unroll
    for (int mf = 0; mf < 4; mf++)
#pragma unroll
        for (int nf = 0; nf < 4; nf++)
#pragma unroll
            for (int j = 0; j < 4; j++) acc[mf][nf][j] = 0.0f;

    // ---- load one stage (A + B tiles) ----
    auto load_stage = [&](int it, int s) {
        const int kt = it * BK;
        float* as = As + s * TILE_FLOATS;
        float* bs = Bs + s * TILE_FLOATS;
#pragma unroll
        for (int i = 0; i < 4; i++) {
            int row = lrow + i * 32;
            cp_async16(smem_u32(as + row * ASTRIDE + lch * 4),
                       gA + (size_t)row * IN_F + kt + lch * 4);
        }
#pragma unroll
        for (int i = 0; i < 4; i++) {
            int row = lrow + i * 32;
            cp_async16(smem_u32(bs + row * ASTRIDE + lch * 4),
                       gB + (size_t)row * IN_F + kt + lch * 4);
        }
        asm volatile("cp.async.commit_group;" ::: "memory");
    };

    // prologue: stages 0, 1
    load_stage(0, 0);
    load_stage(1, 1);

#pragma unroll 1
    for (int it = 0; it < NITER; ++it) {
        if (it == NITER - 1)
            asm volatile("cp.async.wait_group 0;" ::: "memory");
        else
            asm volatile("cp.async.wait_group 1;" ::: "memory");
        __syncthreads();

        if (it + 2 < NITER) load_stage(it + 2, (it + 2) % STAGES);

        const int s = it % STAGES;
        const float* as = As + s * TILE_FLOATS + (wm * 64 + g4) * ASTRIDE;
        const float* bs = Bs + s * TILE_FLOATS + (wn * 32 + g4) * ASTRIDE;

#pragma unroll
        for (int ks = 0; ks < 4; ks++) {
            const int kc = ks * 8 + l4;
            uint32_t a[4][4], b[4][2];
#pragma unroll
            for (int mf = 0; mf < 4; mf++) {
                const float* p = as + mf * 16 * ASTRIDE;
                a[mf][0] = __float_as_uint(p[kc]);
                a[mf][1] = __float_as_uint(p[8 * ASTRIDE + kc]);
                a[mf][2] = __float_as_uint(p[kc + 4]);
                a[mf][3] = __float_as_uint(p[8 * ASTRIDE + kc + 4]);
            }
#pragma unroll
            for (int nf = 0; nf < 4; nf++) {
                const float* p = bs + nf * 8 * ASTRIDE;
                b[nf][0] = __float_as_uint(p[kc]);
                b[nf][1] = __float_as_uint(p[kc + 4]);
            }
#pragma unroll
            for (int mf = 0; mf < 4; mf++)
#pragma unroll
                for (int nf = 0; nf < 4; nf++)
                    mma_tf32(acc[mf][nf], a[mf], b[nf]);
        }
    }

    // ---- epilogue: bias add + store ----
    const int m0 = blockIdx.y * BM + wm * 64;
    const int n0 = blockIdx.x * BN + wn * 32;

    float2 bb[4];
#pragma unroll
    for (int nf = 0; nf < 4; nf++)
        bb[nf] = *(const float2*)(bias + n0 + nf * 8 + l4 * 2);

#pragma unroll
    for (int mf = 0; mf < 4; mf++) {
        const int m = m0 + mf * 16 + g4;
        float* r0 = out + (size_t)m * OUT_F;
        float* r1 = out + (size_t)(m + 8) * OUT_F;
#pragma unroll
        for (int nf = 0; nf < 4; nf++) {
            const int n = n0 + nf * 8 + l4 * 2;
            float2 v0, v1;
            v0.x = acc[mf][nf][0] + bb[nf].x;
            v0.y = acc[mf][nf][1] + bb[nf].y;
            v1.x = acc[mf][nf][2] + bb[nf].x;
            v1.y = acc[mf][nf][3] + bb[nf].y;
            *(float2*)(r0 + n) = v0;
            *(float2*)(r1 + n) = v1;
        }
    }
}

// ---------------------------------------------------------------------------
// Launch: x, qweight, scales, bias, lora_A, lora_B
// ---------------------------------------------------------------------------
extern "C" void kernel_launch(void* const* d_in, const int* in_sizes, int n_in,
                              void* d_out, int out_size)
{
    const float* x      = (const float*)d_in[0];
    const int*   qw     = (const int*)  d_in[1];
    const float* scales = (const float*)d_in[2];
    const float* bias   = (const float*)d_in[3];
    const float* lora_A = (const float*)d_in[4];
    const float* lora_B = (const float*)d_in[5];
    float*       out    = (float*)d_out;
    (void)in_sizes; (void)n_in; (void)out_size;

    cudaFuncSetAttribute(gemm_tf32_kernel,
                         cudaFuncAttributeMaxDynamicSharedMemorySize, SMEM_BYTES);

    dequant_lora_kernel<<<(OUT_F * IN_F / 2) / 256, 256>>>(qw, scales, lora_A, lora_B);
    convert_x_kernel<<<(M_TOK * IN_F / 4) / 256, 256>>>(x);

    dim3 grid(OUT_F / BN, M_TOK / BM);      // (32, 16)
    gemm_tf32_kernel<<<grid, 256, SMEM_BYTES>>>(bias, out);
}

// round 4
// speedup vs baseline: 3.8793x; 1.2020x over previous
#include <cuda_runtime.h>
#include <cstdint>

// ---------------------------------------------------------------------------
// BaseLoftqLinear:
//   W' = dequant4(q, s) + 2.0 * (B @ A)      (LoRA folded into weights)
//   out = x @ W'^T + bias
// GEMM via mma.sync tf32 + ldmatrix (non-'a' PTX feature set).
// ---------------------------------------------------------------------------

#define OUT_F 4096
#define IN_F  4096
#define M_TOK 2048
#define R_LORA 16

__device__ float g_W[(size_t)OUT_F * IN_F];   // tf32-rounded merged weights
__device__ float g_X[(size_t)M_TOK * IN_F];   // tf32-rounded activations

__device__ __forceinline__ float tf32_rna(float v) {
    uint32_t r;
    asm("cvt.rna.tf32.f32 %0, %1;" : "=r"(r) : "f"(v));
    return __uint_as_float(r);
}

__device__ __forceinline__ uint32_t smem_u32(const void* p) {
    uint32_t a;
    asm("{ .reg .u64 t; cvta.to.shared.u64 t, %1; cvt.u32.u64 %0, t; }"
        : "=r"(a) : "l"(p));
    return a;
}

// ---------------------------------------------------------------------------
// Kernel 1: tiled dequant + LoRA fold -> tf32-rounded fp32 W'
// Block tile: 32 rows (o) x 512 cols (k). lora_A tile + lora_B tile in SMEM.
// Thread t: rows {ro, ro+16}, cols {4*tt + 64*jb : jb=0..7}  (tt = t&15).
// ---------------------------------------------------------------------------
#define DQ_BM 32
#define DQ_BK 512

__global__ __launch_bounds__(256)
void dequant_lora_kernel(const int* __restrict__ qweight,
                         const float* __restrict__ scales,
                         const float* __restrict__ lora_A,   // [R, IN_F]
                         const float* __restrict__ lora_B)   // [OUT_F, R]
{
    __shared__ float sA[R_LORA * DQ_BK];   // [16][512]  32 KB
    __shared__ float sB[DQ_BM * R_LORA];   // [32][16]    2 KB

    const int t  = threadIdx.x;
    const int bo = blockIdx.y * DQ_BM;
    const int bk = blockIdx.x * DQ_BK;

    // stage lora_A tile: 8192 floats = 2048 float4, 8 per thread
#pragma unroll
    for (int i = 0; i < 8; i++) {
        int id  = t + i * 256;              // 0..2047
        int r   = id >> 7;                  // 0..15
        int c4  = id & 127;                 // float4 col
        *(float4*)(sA + r * DQ_BK + c4 * 4) =
            *(const float4*)(lora_A + (size_t)r * IN_F + bk + c4 * 4);
    }
    // stage lora_B tile: 512 floats = 128 float4
    if (t < 128)
        *(float4*)(sB + t * 4) = *(const float4*)(lora_B + (size_t)bo * R_LORA + t * 4);
    __syncthreads();

    const int ro = t >> 4;                  // 0..15
    const int tt = t & 15;

    float B0[R_LORA], B1[R_LORA];
#pragma unroll
    for (int r = 0; r < R_LORA; r++) {
        B0[r] = 2.0f * sB[ro * R_LORA + r];
        B1[r] = 2.0f * sB[(ro + 16) * R_LORA + r];
    }

    const int row0 = bo + ro;
    const int row1 = bo + ro + 16;
    const float step = 2.0f / 15.0f;

#pragma unroll
    for (int jb = 0; jb < 8; jb++) {
        const int c = tt * 4 + jb * 64;     // col within tile (0..508)

        // lora term for 4 cols, both rows
        float4 l0 = {0, 0, 0, 0}, l1 = {0, 0, 0, 0};
#pragma unroll
        for (int r = 0; r < R_LORA; r++) {
            float4 a = *(const float4*)(sA + r * DQ_BK + c);
            l0.x = fmaf(B0[r], a.x, l0.x); l0.y = fmaf(B0[r], a.y, l0.y);
            l0.z = fmaf(B0[r], a.z, l0.z); l0.w = fmaf(B0[r], a.w, l0.w);
            l1.x = fmaf(B1[r], a.x, l1.x); l1.y = fmaf(B1[r], a.y, l1.y);
            l1.z = fmaf(B1[r], a.z, l1.z); l1.w = fmaf(B1[r], a.w, l1.w);
        }

        // dequant 4 weights per row (2 qweight ints = int2)
        const int gc = bk + c;              // global col
        const float s0 = scales[(row0 << 6) + (gc >> 6)];
        const float s1 = scales[(row1 << 6) + (gc >> 6)];
        int2 q0 = *(const int2*)(qweight + (size_t)row0 * (IN_F / 2) + (gc >> 1));
        int2 q1 = *(const int2*)(qweight + (size_t)row1 * (IN_F / 2) + (gc >> 1));

        float4 w0, w1;
        w0.x = fmaf(fmaf((float)(q0.x & 15),        step, -1.0f), s0, l0.x);
        w0.y = fmaf(fmaf((float)((q0.x >> 4) & 15), step, -1.0f), s0, l0.y);
        w0.z = fmaf(fmaf((float)(q0.y & 15),        step, -1.0f), s0, l0.z);
        w0.w = fmaf(fmaf((float)((q0.y >> 4) & 15), step, -1.0f), s0, l0.w);
        w1.x = fmaf(fmaf((float)(q1.x & 15),        step, -1.0f), s1, l1.x);
        w1.y = fmaf(fmaf((float)((q1.x >> 4) & 15), step, -1.0f), s1, l1.y);
        w1.z = fmaf(fmaf((float)(q1.y & 15),        step, -1.0f), s1, l1.z);
        w1.w = fmaf(fmaf((float)((q1.y >> 4) & 15), step, -1.0f), s1, l1.w);

        w0.x = tf32_rna(w0.x); w0.y = tf32_rna(w0.y);
        w0.z = tf32_rna(w0.z); w0.w = tf32_rna(w0.w);
        w1.x = tf32_rna(w1.x); w1.y = tf32_rna(w1.y);
        w1.z = tf32_rna(w1.z); w1.w = tf32_rna(w1.w);

        *(float4*)(g_W + (size_t)row0 * IN_F + gc) = w0;
        *(float4*)(g_W + (size_t)row1 * IN_F + gc) = w1;
    }
}

// ---------------------------------------------------------------------------
// Kernel 2: tf32-round x
// ---------------------------------------------------------------------------
__global__ __launch_bounds__(256)
void convert_x_kernel(const float* __restrict__ x)
{
    int i = (blockIdx.x * 256 + threadIdx.x) * 4;
    float4 v = *(const float4*)(x + i);
    float4 r;
    r.x = tf32_rna(v.x); r.y = tf32_rna(v.y);
    r.z = tf32_rna(v.z); r.w = tf32_rna(v.w);
    *(float4*)(g_X + i) = r;
}

// ---------------------------------------------------------------------------
// Kernel 3: tf32 tensor-core GEMM  out[M,N] = X @ W'^T + bias
// CTA 128x128, BK=32, 3-stage cp.async, 8 warps (2M x 4N), warp tile 64x32,
// mma.sync.m16n8k8, ldmatrix fragment loads.
// ---------------------------------------------------------------------------
#define BM 128
#define BN 128
#define BK 32
#define NITER (IN_F / BK)          // 128
#define STAGES 3
#define ASTRIDE 36                 // floats per smem row
#define TILE_FLOATS (128 * ASTRIDE)
#define SMEM_BYTES (2 * STAGES * TILE_FLOATS * 4)   // 110592

__device__ __forceinline__ void cp_async16(uint32_t dst, const float* src) {
    asm volatile("cp.async.cg.shared.global [%0], [%1], 16;"
                 :: "r"(dst), "l"(src) : "memory");
}

__device__ __forceinline__ void ldmx4(uint32_t* r, uint32_t addr) {
    asm volatile("ldmatrix.sync.aligned.m8n8.x4.shared.b16 {%0,%1,%2,%3}, [%4];"
                 : "=r"(r[0]), "=r"(r[1]), "=r"(r[2]), "=r"(r[3]) : "r"(addr));
}

__device__ __forceinline__ void mma_tf32(float* d, const uint32_t* a,
                                         uint32_t b0, uint32_t b1) {
    asm volatile(
        "mma.sync.aligned.m16n8k8.row.col.f32.tf32.tf32.f32 "
        "{%0,%1,%2,%3}, {%4,%5,%6,%7}, {%8,%9}, {%0,%1,%2,%3};"
        : "+f"(d[0]), "+f"(d[1]), "+f"(d[2]), "+f"(d[3])
        : "r"(a[0]), "r"(a[1]), "r"(a[2]), "r"(a[3]), "r"(b0), "r"(b1));
}

__global__ __launch_bounds__(256, 2)
void gemm_tf32_kernel(const float* __restrict__ bias, float* __restrict__ out)
{
    extern __shared__ float smem[];
    float* As = smem;                            // [STAGES][128][ASTRIDE]
    float* Bs = smem + STAGES * TILE_FLOATS;

    const int t    = threadIdx.x;
    const int lane = t & 31;
    const int wid  = t >> 5;
    const int g4   = lane >> 2;
    const int l4   = lane & 3;
    const int wm   = wid & 1;
    const int wn   = wid >> 1;

    const float* gA = g_X + (size_t)(blockIdx.y * BM) * IN_F;
    const float* gB = g_W + (size_t)(blockIdx.x * BN) * IN_F;

    const int lrow = t >> 3;
    const int lch  = t & 7;

    // ldmatrix per-lane byte offsets (within a stage's tile)
    const int ar = lane & 7;
    const int ag = lane >> 3;                    // 0..3
    // A: m0=a0(rows+0,k+0) m1=a1(rows+8,k+0) m2=a2(rows+0,k+4) m3=a3(rows+8,k+4)
    const uint32_t a_lane =
        ((uint32_t)((wm * 64 + (ag & 1) * 8 + ar) * ASTRIDE + (ag >> 1) * 4)) * 4u;
    // B: m0=nf0.b0(rows+0,k+0) m1=nf0.b1(rows+0,k+4) m2=nf1.b0(rows+8,k+0) m3=nf1.b1(rows+8,k+4)
    const uint32_t b_lane =
        ((uint32_t)((wn * 32 + (ag >> 1) * 8 + ar) * ASTRIDE + (ag & 1) * 4)) * 4u;

    const uint32_t As_u32 = smem_u32(As);
    const uint32_t Bs_u32 = smem_u32(Bs);

    float acc[4][4][4];
#pragma unroll
    for (int mf = 0; mf < 4; mf++)
#pragma unroll
        for (int nf = 0; nf < 4; nf++)
#pragma unroll
            for (int j = 0; j < 4; j++) acc[mf][nf][j] = 0.0f;

    auto load_stage = [&](int it, int s) {
        const int kt = it * BK;
        float* as = As + s * TILE_FLOATS;
        float* bs = Bs + s * TILE_FLOATS;
#pragma unroll
        for (int i = 0; i < 4; i++) {
            int row = lrow + i * 32;
            cp_async16(smem_u32(as + row * ASTRIDE + lch * 4),
                       gA + (size_t)row * IN_F + kt + lch * 4);
        }
#pragma unroll
        for (int i = 0; i < 4; i++) {
            int row = lrow + i * 32;
            cp_async16(smem_u32(bs + row * ASTRIDE + lch * 4),
                       gB + (size_t)row * IN_F + kt + lch * 4);
        }
        asm volatile("cp.async.commit_group;" ::: "memory");
    };

    load_stage(0, 0);
    load_stage(1, 1);

#pragma unroll 1
    for (int it = 0; it < NITER; ++it) {
        if (it == NITER - 1)
            asm volatile("cp.async.wait_group 0;" ::: "memory");
        else
            asm volatile("cp.async.wait_group 1;" ::: "memory");
        __syncthreads();

        if (it + 2 < NITER) load_stage(it + 2, (it + 2) % STAGES);

        const int s = it % STAGES;
        const uint32_t aS = As_u32 + s * TILE_FLOATS * 4 + a_lane;
        const uint32_t bS = Bs_u32 + s * TILE_FLOATS * 4 + b_lane;

#pragma unroll
        for (int ks = 0; ks < 4; ks++) {
            uint32_t a[4][4], b[2][4];
#pragma unroll
            for (int mf = 0; mf < 4; mf++)
                ldmx4(a[mf], aS + (uint32_t)(mf * 16 * ASTRIDE + ks * 8) * 4u);
#pragma unroll
            for (int p = 0; p < 2; p++)
                ldmx4(b[p], bS + (uint32_t)(p * 16 * ASTRIDE + ks * 8) * 4u);

#pragma unroll
            for (int mf = 0; mf < 4; mf++) {
                mma_tf32(acc[mf][0], a[mf], b[0][0], b[0][1]);
                mma_tf32(acc[mf][1], a[mf], b[0][2], b[0][3]);
                mma_tf32(acc[mf][2], a[mf], b[1][0], b[1][1]);
                mma_tf32(acc[mf][3], a[mf], b[1][2], b[1][3]);
            }
        }
    }

    // ---- epilogue: bias add + store ----
    const int m0 = blockIdx.y * BM + wm * 64;
    const int n0 = blockIdx.x * BN + wn * 32;

    float2 bb[4];
#pragma unroll
    for (int nf = 0; nf < 4; nf++)
        bb[nf] = *(const float2*)(bias + n0 + nf * 8 + l4 * 2);

#pragma unroll
    for (int mf = 0; mf < 4; mf++) {
        const int m = m0 + mf * 16 + g4;
        float* r0 = out + (size_t)m * OUT_F;
        float* r1 = out + (size_t)(m + 8) * OUT_F;
#pragma unroll
        for (int nf = 0; nf < 4; nf++) {
            const int n = n0 + nf * 8 + l4 * 2;
            float2 v0, v1;
            v0.x = acc[mf][nf][0] + bb[nf].x;
            v0.y = acc[mf][nf][1] + bb[nf].y;
            v1.x = acc[mf][nf][2] + bb[nf].x;
            v1.y = acc[mf][nf][3] + bb[nf].y;
            *(float2*)(r0 + n) = v0;
            *(float2*)(r1 + n) = v1;
        }
    }
}

// ---------------------------------------------------------------------------
// Launch: x, qweight, scales, bias, lora_A, lora_B
// ---------------------------------------------------------------------------
extern "C" void kernel_launch(void* const* d_in, const int* in_sizes, int n_in,
                              void* d_out, int out_size)
{
    const float* x      = (const float*)d_in[0];
    const int*   qw     = (const int*)  d_in[1];
    const float* scales = (const float*)d_in[2];
    const float* bias   = (const float*)d_in[3];
    const float* lora_A = (const float*)d_in[4];
    const float* lora_B = (const float*)d_in[5];
    float*       out    = (float*)d_out;
    (void)in_sizes; (void)n_in; (void)out_size;

    cudaFuncSetAttribute(gemm_tf32_kernel,
                         cudaFuncAttributeMaxDynamicSharedMemorySize, SMEM_BYTES);

    dim3 dq_grid(IN_F / DQ_BK, OUT_F / DQ_BM);   // (8, 128)
    dequant_lora_kernel<<<dq_grid, 256>>>(qw, scales, lora_A, lora_B);
    convert_x_kernel<<<(M_TOK * IN_F / 4) / 256, 256>>>(x);

    dim3 grid(OUT_F / BN, M_TOK / BM);           // (32, 16)
    gemm_tf32_kernel<<<grid, 256, SMEM_BYTES>>>(bias, out);
}

// round 5
// speedup vs baseline: 4.8233x; 1.2433x over previous
#include <cuda_runtime.h>
#include <cuda_fp16.h>
#include <cstdint>

// ---------------------------------------------------------------------------
// BaseLoftqLinear:
//   W' = dequant4(q, s) + 2.0 * (B @ A)      (LoRA folded into weights)
//   out = x @ W'^T + bias
// GEMM via mma.sync.m16n8k16 fp16 (11-bit mantissa == tf32, 2x throughput),
// fp32 accumulation. Non-'a' PTX feature set only.
// ---------------------------------------------------------------------------

#define OUT_F 4096
#define IN_F  4096
#define M_TOK 2048
#define R_LORA 16

__device__ __half g_W[(size_t)OUT_F * IN_F];   // fp16 merged weights
__device__ __half g_X[(size_t)M_TOK * IN_F];   // fp16 activations

__device__ __forceinline__ uint32_t smem_u32(const void* p) {
    uint32_t a;
    asm("{ .reg .u64 t; cvta.to.shared.u64 t, %1; cvt.u32.u64 %0, t; }"
        : "=r"(a) : "l"(p));
    return a;
}

// ---------------------------------------------------------------------------
// Kernel 1: tiled dequant + LoRA fold -> fp16 W'
// Block tile: 32 rows (o) x 512 cols (k); lora_A/lora_B staged in SMEM.
// ---------------------------------------------------------------------------
#define DQ_BM 32
#define DQ_BK 512

__global__ __launch_bounds__(256)
void dequant_lora_kernel(const int* __restrict__ qweight,
                         const float* __restrict__ scales,
                         const float* __restrict__ lora_A,   // [R, IN_F]
                         const float* __restrict__ lora_B)   // [OUT_F, R]
{
    __shared__ float sA[R_LORA * DQ_BK];   // 32 KB
    __shared__ float sB[DQ_BM * R_LORA];   //  2 KB

    const int t  = threadIdx.x;
    const int bo = blockIdx.y * DQ_BM;
    const int bk = blockIdx.x * DQ_BK;

#pragma unroll
    for (int i = 0; i < 8; i++) {
        int id  = t + i * 256;
        int r   = id >> 7;
        int c4  = id & 127;
        *(float4*)(sA + r * DQ_BK + c4 * 4) =
            *(const float4*)(lora_A + (size_t)r * IN_F + bk + c4 * 4);
    }
    if (t < 128)
        *(float4*)(sB + t * 4) = *(const float4*)(lora_B + (size_t)bo * R_LORA + t * 4);
    __syncthreads();

    const int ro = t >> 4;
    const int tt = t & 15;

    float B0[R_LORA], B1[R_LORA];
#pragma unroll
    for (int r = 0; r < R_LORA; r++) {
        B0[r] = 2.0f * sB[ro * R_LORA + r];
        B1[r] = 2.0f * sB[(ro + 16) * R_LORA + r];
    }

    const int row0 = bo + ro;
    const int row1 = bo + ro + 16;
    const float step = 2.0f / 15.0f;

#pragma unroll
    for (int jb = 0; jb < 8; jb++) {
        const int c = tt * 4 + jb * 64;

        float4 l0 = {0, 0, 0, 0}, l1 = {0, 0, 0, 0};
#pragma unroll
        for (int r = 0; r < R_LORA; r++) {
            float4 a = *(const float4*)(sA + r * DQ_BK + c);
            l0.x = fmaf(B0[r], a.x, l0.x); l0.y = fmaf(B0[r], a.y, l0.y);
            l0.z = fmaf(B0[r], a.z, l0.z); l0.w = fmaf(B0[r], a.w, l0.w);
            l1.x = fmaf(B1[r], a.x, l1.x); l1.y = fmaf(B1[r], a.y, l1.y);
            l1.z = fmaf(B1[r], a.z, l1.z); l1.w = fmaf(B1[r], a.w, l1.w);
        }

        const int gc = bk + c;
        const float s0 = scales[(row0 << 6) + (gc >> 6)];
        const float s1 = scales[(row1 << 6) + (gc >> 6)];
        int2 q0 = *(const int2*)(qweight + (size_t)row0 * (IN_F / 2) + (gc >> 1));
        int2 q1 = *(const int2*)(qweight + (size_t)row1 * (IN_F / 2) + (gc >> 1));

        float4 w0, w1;
        w0.x = fmaf(fmaf((float)(q0.x & 15),        step, -1.0f), s0, l0.x);
        w0.y = fmaf(fmaf((float)((q0.x >> 4) & 15), step, -1.0f), s0, l0.y);
        w0.z = fmaf(fmaf((float)(q0.y & 15),        step, -1.0f), s0, l0.z);
        w0.w = fmaf(fmaf((float)((q0.y >> 4) & 15), step, -1.0f), s0, l0.w);
        w1.x = fmaf(fmaf((float)(q1.x & 15),        step, -1.0f), s1, l1.x);
        w1.y = fmaf(fmaf((float)((q1.x >> 4) & 15), step, -1.0f), s1, l1.y);
        w1.z = fmaf(fmaf((float)(q1.y & 15),        step, -1.0f), s1, l1.z);
        w1.w = fmaf(fmaf((float)((q1.y >> 4) & 15), step, -1.0f), s1, l1.w);

        __half2 h0a = __floats2half2_rn(w0.x, w0.y);
        __half2 h0b = __floats2half2_rn(w0.z, w0.w);
        __half2 h1a = __floats2half2_rn(w1.x, w1.y);
        __half2 h1b = __floats2half2_rn(w1.z, w1.w);
        *(__half2*)(g_W + (size_t)row0 * IN_F + gc)     = h0a;
        *(__half2*)(g_W + (size_t)row0 * IN_F + gc + 2) = h0b;
        *(__half2*)(g_W + (size_t)row1 * IN_F + gc)     = h1a;
        *(__half2*)(g_W + (size_t)row1 * IN_F + gc + 2) = h1b;
    }
}

// ---------------------------------------------------------------------------
// Kernel 2: fp16-round x
// ---------------------------------------------------------------------------
__global__ __launch_bounds__(256)
void convert_x_kernel(const float* __restrict__ x)
{
    int i = (blockIdx.x * 256 + threadIdx.x) * 8;
    float4 v0 = *(const float4*)(x + i);
    float4 v1 = *(const float4*)(x + i + 4);
    __half2 h0 = __floats2half2_rn(v0.x, v0.y);
    __half2 h1 = __floats2half2_rn(v0.z, v0.w);
    __half2 h2 = __floats2half2_rn(v1.x, v1.y);
    __half2 h3 = __floats2half2_rn(v1.z, v1.w);
    __half2* p = (__half2*)(g_X + i);
    p[0] = h0; p[1] = h1; p[2] = h2; p[3] = h3;
}

// ---------------------------------------------------------------------------
// Kernel 3: fp16 tensor-core GEMM  out[M,N] = X @ W'^T + bias
// CTA 128x128, BK=64, 3-stage cp.async, 8 warps (2M x 4N), warp tile 64x32,
// mma.sync.m16n8k16 fp16->fp32, ldmatrix fragment loads.
// ---------------------------------------------------------------------------
#define BM 128
#define BN 128
#define BK 64
#define NITER (IN_F / BK)          // 64
#define STAGES 3
#define KSTRIDE 72                 // halfs per smem row (144B; banks 4r mod 32)
#define TILE_HALFS (128 * KSTRIDE)
#define SMEM_BYTES (2 * STAGES * TILE_HALFS * 2)   // 110592

__device__ __forceinline__ void cp_async16(uint32_t dst, const void* src) {
    asm volatile("cp.async.cg.shared.global [%0], [%1], 16;"
                 :: "r"(dst), "l"(src) : "memory");
}

__device__ __forceinline__ void ldmx4(uint32_t* r, uint32_t addr) {
    asm volatile("ldmatrix.sync.aligned.m8n8.x4.shared.b16 {%0,%1,%2,%3}, [%4];"
                 : "=r"(r[0]), "=r"(r[1]), "=r"(r[2]), "=r"(r[3]) : "r"(addr));
}

__device__ __forceinline__ void mma_f16(float* d, const uint32_t* a,
                                        uint32_t b0, uint32_t b1) {
    asm volatile(
        "mma.sync.aligned.m16n8k16.row.col.f32.f16.f16.f32 "
        "{%0,%1,%2,%3}, {%4,%5,%6,%7}, {%8,%9}, {%0,%1,%2,%3};"
        : "+f"(d[0]), "+f"(d[1]), "+f"(d[2]), "+f"(d[3])
        : "r"(a[0]), "r"(a[1]), "r"(a[2]), "r"(a[3]), "r"(b0), "r"(b1));
}

__global__ __launch_bounds__(256, 2)
void gemm_f16_kernel(const float* __restrict__ bias, float* __restrict__ out)
{
    extern __shared__ __half smem[];
    __half* As = smem;                           // [STAGES][128][KSTRIDE]
    __half* Bs = smem + STAGES * TILE_HALFS;

    const int t    = threadIdx.x;
    const int lane = t & 31;
    const int wid  = t >> 5;
    const int g4   = lane >> 2;
    const int l4   = lane & 3;
    const int wm   = wid & 1;
    const int wn   = wid >> 1;

    const __half* gA = g_X + (size_t)(blockIdx.y * BM) * IN_F;
    const __half* gB = g_W + (size_t)(blockIdx.x * BN) * IN_F;

    // loader: 1024 16B-chunks per tile (128 rows x 8 chunks), 4 per thread
    const int lrow = t >> 1;                     // rows 0..127 (2 thr/row)
    const int lch  = (t & 1) * 4;                // chunk 0-3 or 4-7 base

    // ldmatrix per-lane byte offsets
    const int ar = lane & 7;
    const int ag = lane >> 3;                    // 0..3
    const uint32_t frag_lane =
        (uint32_t)(((ag & 1) * 8 + ar) * KSTRIDE + (ag >> 1) * 8) * 2u;
    const uint32_t a_lane = (uint32_t)(wm * 64 * KSTRIDE) * 2u + frag_lane;
    const uint32_t b_lane = (uint32_t)(wn * 32 * KSTRIDE) * 2u + frag_lane;

    const uint32_t As_u32 = smem_u32(As);
    const uint32_t Bs_u32 = smem_u32(Bs);

    float acc[4][4][4];
#pragma unroll
    for (int mf = 0; mf < 4; mf++)
#pragma unroll
        for (int nf = 0; nf < 4; nf++)
#pragma unroll
            for (int j = 0; j < 4; j++) acc[mf][nf][j] = 0.0f;

    auto load_stage = [&](int it, int s) {
        const int kt = it * BK;
        __half* as = As + s * TILE_HALFS + lrow * KSTRIDE;
        __half* bs = Bs + s * TILE_HALFS + lrow * KSTRIDE;
        const __half* ga = gA + (size_t)lrow * IN_F + kt;
        const __half* gb = gB + (size_t)lrow * IN_F + kt;
#pragma unroll
        for (int i = 0; i < 4; i++) {
            int ch = lch + i;                    // 16B chunk index 0..7
            cp_async16(smem_u32(as + ch * 8), ga + ch * 8);
        }
#pragma unroll
        for (int i = 0; i < 4; i++) {
            int ch = lch + i;
            cp_async16(smem_u32(bs + ch * 8), gb + ch * 8);
        }
        asm volatile("cp.async.commit_group;" ::: "memory");
    };

    load_stage(0, 0);
    load_stage(1, 1);

#pragma unroll 1
    for (int it = 0; it < NITER; ++it) {
        if (it == NITER - 1)
            asm volatile("cp.async.wait_group 0;" ::: "memory");
        else
            asm volatile("cp.async.wait_group 1;" ::: "memory");
        __syncthreads();

        if (it + 2 < NITER) load_stage(it + 2, (it + 2) % STAGES);

        const int s = it % STAGES;
        const uint32_t aS = As_u32 + s * TILE_HALFS * 2 + a_lane;
        const uint32_t bS = Bs_u32 + s * TILE_HALFS * 2 + b_lane;

#pragma unroll
        for (int ks = 0; ks < 4; ks++) {         // k16 steps within BK=64
            uint32_t a[4][4], b[2][4];
#pragma unroll
            for (int mf = 0; mf < 4; mf++)
                ldmx4(a[mf], aS + (uint32_t)(mf * 16 * KSTRIDE * 2 + ks * 32));
#pragma unroll
            for (int p = 0; p < 2; p++)
                ldmx4(b[p], bS + (uint32_t)(p * 16 * KSTRIDE * 2 + ks * 32));

#pragma unroll
            for (int mf = 0; mf < 4; mf++) {
                mma_f16(acc[mf][0], a[mf], b[0][0], b[0][2]);
                mma_f16(acc[mf][1], a[mf], b[0][1], b[0][3]);
                mma_f16(acc[mf][2], a[mf], b[1][0], b[1][2]);
                mma_f16(acc[mf][3], a[mf], b[1][1], b[1][3]);
            }
        }
    }

    // ---- epilogue: bias add + store ----
    const int m0 = blockIdx.y * BM + wm * 64;
    const int n0 = blockIdx.x * BN + wn * 32;

    float2 bb[4];
#pragma unroll
    for (int nf = 0; nf < 4; nf++)
        bb[nf] = *(const float2*)(bias + n0 + nf * 8 + l4 * 2);

#pragma unroll
    for (int mf = 0; mf < 4; mf++) {
        const int m = m0 + mf * 16 + g4;
        float* r0 = out + (size_t)m * OUT_F;
        float* r1 = out + (size_t)(m + 8) * OUT_F;
#pragma unroll
        for (int nf = 0; nf < 4; nf++) {
            const int n = n0 + nf * 8 + l4 * 2;
            float2 v0, v1;
            v0.x = acc[mf][nf][0] + bb[nf].x;
            v0.y = acc[mf][nf][1] + bb[nf].y;
            v1.x = acc[mf][nf][2] + bb[nf].x;
            v1.y = acc[mf][nf][3] + bb[nf].y;
            *(float2*)(r0 + n) = v0;
            *(float2*)(r1 + n) = v1;
        }
    }
}

// ---------------------------------------------------------------------------
// Launch: x, qweight, scales, bias, lora_A, lora_B
// ---------------------------------------------------------------------------
extern "C" void kernel_launch(void* const* d_in, const int* in_sizes, int n_in,
                              void* d_out, int out_size)
{
    const float* x      = (const float*)d_in[0];
    const int*   qw     = (const int*)  d_in[1];
    const float* scales = (const float*)d_in[2];
    const float* bias   = (const float*)d_in[3];
    const float* lora_A = (const float*)d_in[4];
    const float* lora_B = (const float*)d_in[5];
    float*       out    = (float*)d_out;
    (void)in_sizes; (void)n_in; (void)out_size;

    cudaFuncSetAttribute(gemm_f16_kernel,
                         cudaFuncAttributeMaxDynamicSharedMemorySize, SMEM_BYTES);

    dim3 dq_grid(IN_F / DQ_BK, OUT_F / DQ_BM);   // (8, 128)
    dequant_lora_kernel<<<dq_grid, 256>>>(qw, scales, lora_A, lora_B);
    convert_x_kernel<<<(M_TOK * IN_F / 8) / 256, 256>>>(x);

    dim3 grid(OUT_F / BN, M_TOK / BM);           // (32, 16)
    gemm_f16_kernel<<<grid, 256, SMEM_BYTES>>>(bias, out);
}

// round 7
// speedup vs baseline: 7.3139x; 1.5164x over previous
#include <cuda_runtime.h>
#include <cuda_fp16.h>
#include <cstdint>

// ---------------------------------------------------------------------------
// BaseLoftqLinear:
//   W' = dequant4(q, s) + 2.0 * (B @ A)      (LoRA folded into weights)
//   out = x @ W'^T + bias
// fp16 mma.sync.m16n8k16 (fp32 accum). Operands pre-packed & pre-swizzled in
// GEMM smem-tile order so the mainloop loader is pure linear cp.async.
// ---------------------------------------------------------------------------

#define OUT_F 4096
#define IN_F  4096
#define M_TOK 2048
#define R_LORA 16

// packed 16B-chunk layouts:
//   X: [mt(16)][kt(64)][row(128)][chunk(8)]   chunk stored at (ch ^ (row&7))
//   W: [nt(16)][kt(64)][row(256)][chunk(8)]   chunk stored at (ch ^ (row&7))
__device__ uint4 g_Xp[(size_t)M_TOK * IN_F / 8];   // 16 MB
__device__ uint4 g_Wp[(size_t)OUT_F * IN_F / 8];   // 32 MB

__device__ __forceinline__ uint32_t smem_u32(const void* p) {
    uint32_t a;
    asm("{ .reg .u64 t; cvta.to.shared.u64 t, %1; cvt.u32.u64 %0, t; }"
        : "=r"(a) : "l"(p));
    return a;
}

__device__ __forceinline__ uint32_t h2_u32(__half2 h) {
    union { __half2 h; uint32_t u; } cvt;
    cvt.h = h;
    return cvt.u;
}

// ---------------------------------------------------------------------------
// Prep kernel (fused): blocks 0..1023 = W tiles, 1024..2047 = X tiles.
// ---------------------------------------------------------------------------
__global__ __launch_bounds__(256)
void prep_kernel(const float* __restrict__ x,
                 const int* __restrict__ qweight,
                 const float* __restrict__ scales,
                 const float* __restrict__ lora_A,   // [R, IN_F]
                 const float* __restrict__ lora_B)   // [OUT_F, R]
{
    const int t = threadIdx.x;
    const int b = blockIdx.x;

    if (b < 1024) {
        // ---- W tile: nt = b>>6, kt = b&63; 256 rows x 64 cols ----
        __shared__ float sA[R_LORA][64];     // lora_A slice for this kt
        const int nt = b >> 6;
        const int kt = b & 63;

        // stage A slice: 16x64 floats = 256 float4
        {
            int r  = t >> 4;
            int c4 = t & 15;
            *(float4*)&sA[r][c4 * 4] =
                *(const float4*)(lora_A + (size_t)r * IN_F + kt * 64 + c4 * 4);
        }
        __syncthreads();

        const int row_g = nt * 256 + t;      // global output row; thread owns row
        // B row into registers (x2 LoRA scale folded)
        float Bv[R_LORA];
        {
            float4 b0 = *(const float4*)(lora_B + (size_t)row_g * R_LORA + 0);
            float4 b1 = *(const float4*)(lora_B + (size_t)row_g * R_LORA + 4);
            float4 b2 = *(const float4*)(lora_B + (size_t)row_g * R_LORA + 8);
            float4 b3 = *(const float4*)(lora_B + (size_t)row_g * R_LORA + 12);
            Bv[0]=2*b0.x; Bv[1]=2*b0.y; Bv[2]=2*b0.z; Bv[3]=2*b0.w;
            Bv[4]=2*b1.x; Bv[5]=2*b1.y; Bv[6]=2*b1.z; Bv[7]=2*b1.w;
            Bv[8]=2*b2.x; Bv[9]=2*b2.y; Bv[10]=2*b2.z; Bv[11]=2*b2.w;
            Bv[12]=2*b3.x; Bv[13]=2*b3.y; Bv[14]=2*b3.z; Bv[15]=2*b3.w;
        }
        const float s = scales[(size_t)row_g * 64 + kt];   // one 64-block per kt
        const float step = 2.0f / 15.0f;

        const uint4* qv = (const uint4*)qweight;           // 4 int32 = 8 weights
        uint4* dst = g_Wp + (size_t)b * 2048 + t * 8;      // this row's 8 chunks

#pragma unroll
        for (int ch = 0; ch < 8; ch++) {
            // lora term for 8 cols
            float l[8] = {0,0,0,0,0,0,0,0};
#pragma unroll
            for (int r = 0; r < R_LORA; r++) {
                float4 a0 = *(const float4*)&sA[r][ch * 8];
                float4 a1 = *(const float4*)&sA[r][ch * 8 + 4];
                l[0] = fmaf(Bv[r], a0.x, l[0]); l[1] = fmaf(Bv[r], a0.y, l[1]);
                l[2] = fmaf(Bv[r], a0.z, l[2]); l[3] = fmaf(Bv[r], a0.w, l[3]);
                l[4] = fmaf(Bv[r], a1.x, l[4]); l[5] = fmaf(Bv[r], a1.y, l[5]);
                l[6] = fmaf(Bv[r], a1.z, l[6]); l[7] = fmaf(Bv[r], a1.w, l[7]);
            }
            // dequant 8 weights: 4 int32, each = 1 byte (2 nibbles)
            uint4 q = qv[(size_t)row_g * 512 + kt * 8 + ch];
            float w[8];
            w[0] = fmaf(fmaf((float)(q.x & 15),        step, -1.0f), s, l[0]);
            w[1] = fmaf(fmaf((float)((q.x >> 4) & 15), step, -1.0f), s, l[1]);
            w[2] = fmaf(fmaf((float)(q.y & 15),        step, -1.0f), s, l[2]);
            w[3] = fmaf(fmaf((float)((q.y >> 4) & 15), step, -1.0f), s, l[3]);
            w[4] = fmaf(fmaf((float)(q.z & 15),        step, -1.0f), s, l[4]);
            w[5] = fmaf(fmaf((float)((q.z >> 4) & 15), step, -1.0f), s, l[5]);
            w[6] = fmaf(fmaf((float)(q.w & 15),        step, -1.0f), s, l[6]);
            w[7] = fmaf(fmaf((float)((q.w >> 4) & 15), step, -1.0f), s, l[7]);

            uint4 o;
            o.x = h2_u32(__floats2half2_rn(w[0], w[1]));
            o.y = h2_u32(__floats2half2_rn(w[2], w[3]));
            o.z = h2_u32(__floats2half2_rn(w[4], w[5]));
            o.w = h2_u32(__floats2half2_rn(w[6], w[7]));
            dst[ch ^ (t & 7)] = o;
        }
    } else {
        // ---- X tile: 128 rows x 64 cols ----
        const int bb = b - 1024;
        const int mt = bb >> 6;
        const int kt = bb & 63;
        uint4* dst = g_Xp + (size_t)bb * 1024;
#pragma unroll
        for (int i = 0; i < 4; i++) {
            int c   = t + i * 256;           // chunk id in tile (0..1023)
            int row = c >> 3;
            int ch  = c & 7;
            const float* src = x + ((size_t)(mt * 128 + row)) * IN_F + kt * 64 + ch * 8;
            float4 v0 = *(const float4*)(src);
            float4 v1 = *(const float4*)(src + 4);
            uint4 o;
            o.x = h2_u32(__floats2half2_rn(v0.x, v0.y));
            o.y = h2_u32(__floats2half2_rn(v0.z, v0.w));
            o.z = h2_u32(__floats2half2_rn(v1.x, v1.y));
            o.w = h2_u32(__floats2half2_rn(v1.z, v1.w));
            dst[row * 8 + (ch ^ (row & 7))] = o;
        }
    }
}

// ---------------------------------------------------------------------------
// GEMM: out[M,N] = X @ W'^T + bias
// CTA 128x256, BK=64, 4-stage cp.async, 8 warps (2M x 4N), warp tile 64x64.
// ---------------------------------------------------------------------------
#define BM 128
#define BN 256
#define BK 64
#define NITER (IN_F / BK)              // 64
#define STAGES 4
#define STAGE_CHUNKS 3072              // A 1024 + B 2048 (16B each)
#define SMEM_BYTES (STAGES * STAGE_CHUNKS * 16)   // 196608

__device__ __forceinline__ void cp_async16(uint32_t dst, const void* src) {
    asm volatile("cp.async.cg.shared.global [%0], [%1], 16;"
                 :: "r"(dst), "l"(src) : "memory");
}

__device__ __forceinline__ void ldmx4(uint32_t* r, uint32_t addr) {
    asm volatile("ldmatrix.sync.aligned.m8n8.x4.shared.b16 {%0,%1,%2,%3}, [%4];"
                 : "=r"(r[0]), "=r"(r[1]), "=r"(r[2]), "=r"(r[3]) : "r"(addr));
}

__device__ __forceinline__ void mma_f16(float* d, const uint32_t* a,
                                        uint32_t b0, uint32_t b1) {
    asm volatile(
        "mma.sync.aligned.m16n8k16.row.col.f32.f16.f16.f32 "
        "{%0,%1,%2,%3}, {%4,%5,%6,%7}, {%8,%9}, {%0,%1,%2,%3};"
        : "+f"(d[0]), "+f"(d[1]), "+f"(d[2]), "+f"(d[3])
        : "r"(a[0]), "r"(a[1]), "r"(a[2]), "r"(a[3]), "r"(b0), "r"(b1));
}

__global__ __launch_bounds__(256, 1)
void gemm_f16_kernel(const float* __restrict__ bias, float* __restrict__ out)
{
    extern __shared__ uint4 smem[];
    const uint32_t sbase = smem_u32(smem);

    const int t    = threadIdx.x;
    const int lane = t & 31;
    const int wid  = t >> 5;
    const int g4   = lane >> 2;
    const int l4   = lane & 3;
    const int wm   = wid & 1;          // 0..1 (M)
    const int wn   = wid >> 1;         // 0..3 (N)
    const int mt   = blockIdx.y;       // 0..15
    const int nt   = blockIdx.x;       // 0..15

    // ldmatrix per-lane constants
    const int ar = lane & 7;
    const int ag = lane >> 3;
    const int rg = ag & 1;             // +8 rows
    const int cg = ag >> 1;            // +1 chunk (k+8)
    const uint32_t arow_off = (uint32_t)(wm * 64 + rg * 8 + ar) * 128u;
    const uint32_t brow_off = (uint32_t)(wn * 64 + rg * 8 + ar) * 128u;
    uint32_t sw[4];
#pragma unroll
    for (int ks = 0; ks < 4; ks++)
        sw[ks] = (uint32_t)(((ks * 2 + cg) ^ ar) * 16);

    const uint4* srcA0 = g_Xp + (size_t)mt * 64 * 1024;
    const uint4* srcB0 = g_Wp + (size_t)nt * 64 * 2048;

    float acc[4][8][4];
#pragma unroll
    for (int mf = 0; mf < 4; mf++)
#pragma unroll
        for (int nf = 0; nf < 8; nf++)
#pragma unroll
            for (int j = 0; j < 4; j++) acc[mf][nf][j] = 0.0f;

    auto load_stage = [&](int it, int s) {
        uint4* dst = smem + s * STAGE_CHUNKS;
        const uint4* sa = srcA0 + (size_t)it * 1024;
        const uint4* sb = srcB0 + (size_t)it * 2048;
        uint32_t d = smem_u32(dst);
#pragma unroll
        for (int i = 0; i < 4; i++)
            cp_async16(d + (t + i * 256) * 16, sa + t + i * 256);
        d += 1024 * 16;
#pragma unroll
        for (int i = 0; i < 8; i++)
            cp_async16(d + (t + i * 256) * 16, sb + t + i * 256);
        asm volatile("cp.async.commit_group;" ::: "memory");
    };

    load_stage(0, 0);
    load_stage(1, 1);
    load_stage(2, 2);

#pragma unroll 1
    for (int it = 0; it < NITER; ++it) {
        if (it < NITER - 2)
            asm volatile("cp.async.wait_group 2;" ::: "memory");
        else if (it == NITER - 2)
            asm volatile("cp.async.wait_group 1;" ::: "memory");
        else
            asm volatile("cp.async.wait_group 0;" ::: "memory");
        __syncthreads();

        if (it + 3 < NITER) load_stage(it + 3, (it + 3) % STAGES);

        const uint32_t aS = sbase + (uint32_t)((it % STAGES) * STAGE_CHUNKS * 16);
        const uint32_t bS = aS + 1024 * 16;

#pragma unroll
        for (int ks = 0; ks < 4; ks++) {
            uint32_t a[4][4], b[4][4];
#pragma unroll
            for (int mf = 0; mf < 4; mf++)
                ldmx4(a[mf], aS + arow_off + mf * 2048 + sw[ks]);
#pragma unroll
            for (int p = 0; p < 4; p++)
                ldmx4(b[p], bS + brow_off + p * 2048 + sw[ks]);

#pragma unroll
            for (int mf = 0; mf < 4; mf++)
#pragma unroll
                for (int p = 0; p < 4; p++) {
                    mma_f16(acc[mf][2 * p],     a[mf], b[p][0], b[p][2]);
                    mma_f16(acc[mf][2 * p + 1], a[mf], b[p][1], b[p][3]);
                }
        }
    }

    // ---- epilogue: bias add + store ----
    const int m0 = mt * BM + wm * 64;
    const int n0 = nt * BN + wn * 64;

    float2 bb[8];
#pragma unroll
    for (int nf = 0; nf < 8; nf++)
        bb[nf] = *(const float2*)(bias + n0 + nf * 8 + l4 * 2);

#pragma unroll
    for (int mf = 0; mf < 4; mf++) {
        const int m = m0 + mf * 16 + g4;
        float* r0 = out + (size_t)m * OUT_F;
        float* r1 = out + (size_t)(m + 8) * OUT_F;
#pragma unroll
        for (int nf = 0; nf < 8; nf++) {
            const int n = n0 + nf * 8 + l4 * 2;
            float2 v0, v1;
            v0.x = acc[mf][nf][0] + bb[nf].x;
            v0.y = acc[mf][nf][1] + bb[nf].y;
            v1.x = acc[mf][nf][2] + bb[nf].x;
            v1.y = acc[mf][nf][3] + bb[nf].y;
            *(float2*)(r0 + n) = v0;
            *(float2*)(r1 + n) = v1;
        }
    }
}

// ---------------------------------------------------------------------------
// Launch: x, qweight, scales, bias, lora_A, lora_B
// ---------------------------------------------------------------------------
extern "C" void kernel_launch(void* const* d_in, const int* in_sizes, int n_in,
                              void* d_out, int out_size)
{
    const float* x      = (const float*)d_in[0];
    const int*   qw     = (const int*)  d_in[1];
    const float* scales = (const float*)d_in[2];
    const float* bias   = (const float*)d_in[3];
    const float* lora_A = (const float*)d_in[4];
    const float* lora_B = (const float*)d_in[5];
    float*       out    = (float*)d_out;
    (void)in_sizes; (void)n_in; (void)out_size;

    cudaFuncSetAttribute(gemm_f16_kernel,
                         cudaFuncAttributeMaxDynamicSharedMemorySize, SMEM_BYTES);

    prep_kernel<<<2048, 256>>>(x, qw, scales, lora_A, lora_B);

    dim3 grid(OUT_F / BN, M_TOK / BM);           // (16, 16)
    gemm_f16_kernel<<<grid, 256, SMEM_BYTES>>>(bias, out);
}

// round 8
// speedup vs baseline: 7.3752x; 1.0084x over previous
#include <cuda_runtime.h>
#include <cuda_fp16.h>
#include <cstdint>

// ---------------------------------------------------------------------------
// BaseLoftqLinear:
//   W' = dequant4(q, s) + 2.0 * (B @ A)      (LoRA folded into weights)
//   out = x @ W'^T + bias
// fp16 mma.sync.m16n8k16 (fp32 accum). Operands pre-packed & pre-swizzled in
// GEMM smem-tile order; GEMM uses 512 threads (16 warps) to keep the tensor
// pipe fed (register-capped at 128/thread so 16 warps fit the RF).
// ---------------------------------------------------------------------------

#define OUT_F 4096
#define IN_F  4096
#define M_TOK 2048
#define R_LORA 16

// packed 16B-chunk layouts:
//   X: [mt(16)][kt(64)][row(128)][chunk(8)]   chunk stored at (ch ^ (row&7))
//   W: [nt(16)][kt(64)][row(256)][chunk(8)]   chunk stored at (ch ^ (row&7))
__device__ uint4 g_Xp[(size_t)M_TOK * IN_F / 8];   // 16 MB
__device__ uint4 g_Wp[(size_t)OUT_F * IN_F / 8];   // 32 MB

__device__ __forceinline__ uint32_t smem_u32(const void* p) {
    uint32_t a;
    asm("{ .reg .u64 t; cvta.to.shared.u64 t, %1; cvt.u32.u64 %0, t; }"
        : "=r"(a) : "l"(p));
    return a;
}

__device__ __forceinline__ uint32_t h2_u32(__half2 h) {
    union { __half2 h; uint32_t u; } cvt;
    cvt.h = h;
    return cvt.u;
}

// ---------------------------------------------------------------------------
// Prep kernel (fused): blocks 0..1023 = W tiles, 1024..2047 = X tiles.
// ---------------------------------------------------------------------------
__global__ __launch_bounds__(256)
void prep_kernel(const float* __restrict__ x,
                 const int* __restrict__ qweight,
                 const float* __restrict__ scales,
                 const float* __restrict__ lora_A,   // [R, IN_F]
                 const float* __restrict__ lora_B)   // [OUT_F, R]
{
    const int t = threadIdx.x;
    const int b = blockIdx.x;

    if (b < 1024) {
        // ---- W tile: nt = b>>6, kt = b&63; 256 rows x 64 cols ----
        __shared__ float sA[R_LORA][64];
        const int nt = b >> 6;
        const int kt = b & 63;

        {
            int r  = t >> 4;
            int c4 = t & 15;
            *(float4*)&sA[r][c4 * 4] =
                *(const float4*)(lora_A + (size_t)r * IN_F + kt * 64 + c4 * 4);
        }
        __syncthreads();

        const int row_g = nt * 256 + t;
        float Bv[R_LORA];
        {
            float4 b0 = *(const float4*)(lora_B + (size_t)row_g * R_LORA + 0);
            float4 b1 = *(const float4*)(lora_B + (size_t)row_g * R_LORA + 4);
            float4 b2 = *(const float4*)(lora_B + (size_t)row_g * R_LORA + 8);
            float4 b3 = *(const float4*)(lora_B + (size_t)row_g * R_LORA + 12);
            Bv[0]=2*b0.x; Bv[1]=2*b0.y; Bv[2]=2*b0.z; Bv[3]=2*b0.w;
            Bv[4]=2*b1.x; Bv[5]=2*b1.y; Bv[6]=2*b1.z; Bv[7]=2*b1.w;
            Bv[8]=2*b2.x; Bv[9]=2*b2.y; Bv[10]=2*b2.z; Bv[11]=2*b2.w;
            Bv[12]=2*b3.x; Bv[13]=2*b3.y; Bv[14]=2*b3.z; Bv[15]=2*b3.w;
        }
        const float s = scales[(size_t)row_g * 64 + kt];
        const float step = 2.0f / 15.0f;

        const uint4* qv = (const uint4*)qweight;
        uint4* dst = g_Wp + (size_t)b * 2048 + t * 8;

#pragma unroll
        for (int ch = 0; ch < 8; ch++) {
            float l[8] = {0,0,0,0,0,0,0,0};
#pragma unroll
            for (int r = 0; r < R_LORA; r++) {
                float4 a0 = *(const float4*)&sA[r][ch * 8];
                float4 a1 = *(const float4*)&sA[r][ch * 8 + 4];
                l[0] = fmaf(Bv[r], a0.x, l[0]); l[1] = fmaf(Bv[r], a0.y, l[1]);
                l[2] = fmaf(Bv[r], a0.z, l[2]); l[3] = fmaf(Bv[r], a0.w, l[3]);
                l[4] = fmaf(Bv[r], a1.x, l[4]); l[5] = fmaf(Bv[r], a1.y, l[5]);
                l[6] = fmaf(Bv[r], a1.z, l[6]); l[7] = fmaf(Bv[r], a1.w, l[7]);
            }
            uint4 q = qv[(size_t)row_g * 512 + kt * 8 + ch];
            float w[8];
            w[0] = fmaf(fmaf((float)(q.x & 15),        step, -1.0f), s, l[0]);
            w[1] = fmaf(fmaf((float)((q.x >> 4) & 15), step, -1.0f), s, l[1]);
            w[2] = fmaf(fmaf((float)(q.y & 15),        step, -1.0f), s, l[2]);
            w[3] = fmaf(fmaf((float)((q.y >> 4) & 15), step, -1.0f), s, l[3]);
            w[4] = fmaf(fmaf((float)(q.z & 15),        step, -1.0f), s, l[4]);
            w[5] = fmaf(fmaf((float)((q.z >> 4) & 15), step, -1.0f), s, l[5]);
            w[6] = fmaf(fmaf((float)(q.w & 15),        step, -1.0f), s, l[6]);
            w[7] = fmaf(fmaf((float)((q.w >> 4) & 15), step, -1.0f), s, l[7]);

            uint4 o;
            o.x = h2_u32(__floats2half2_rn(w[0], w[1]));
            o.y = h2_u32(__floats2half2_rn(w[2], w[3]));
            o.z = h2_u32(__floats2half2_rn(w[4], w[5]));
            o.w = h2_u32(__floats2half2_rn(w[6], w[7]));
            dst[ch ^ (t & 7)] = o;
        }
    } else {
        // ---- X tile: 128 rows x 64 cols ----
        const int bb = b - 1024;
        const int mt = bb >> 6;
        const int kt = bb & 63;
        uint4* dst = g_Xp + (size_t)bb * 1024;
#pragma unroll
        for (int i = 0; i < 4; i++) {
            int c   = t + i * 256;
            int row = c >> 3;
            int ch  = c & 7;
            const float* src = x + ((size_t)(mt * 128 + row)) * IN_F + kt * 64 + ch * 8;
            float4 v0 = *(const float4*)(src);
            float4 v1 = *(const float4*)(src + 4);
            uint4 o;
            o.x = h2_u32(__floats2half2_rn(v0.x, v0.y));
            o.y = h2_u32(__floats2half2_rn(v0.z, v0.w));
            o.z = h2_u32(__floats2half2_rn(v1.x, v1.y));
            o.w = h2_u32(__floats2half2_rn(v1.z, v1.w));
            dst[row * 8 + (ch ^ (row & 7))] = o;
        }
    }
}

// ---------------------------------------------------------------------------
// GEMM: out[M,N] = X @ W'^T + bias
// CTA 128x256, BK=64, 4-stage cp.async, 16 warps (2M x 8N), warp tile 64x32.
// ---------------------------------------------------------------------------
#define BM 128
#define BN 256
#define BK 64
#define NITER (IN_F / BK)              // 64
#define STAGES 4
#define STAGE_CHUNKS 3072              // A 1024 + B 2048 (16B each)
#define SMEM_BYTES (STAGES * STAGE_CHUNKS * 16)   // 196608
#define NTHREADS 512

__device__ __forceinline__ void cp_async16(uint32_t dst, const void* src) {
    asm volatile("cp.async.cg.shared.global [%0], [%1], 16;"
                 :: "r"(dst), "l"(src) : "memory");
}

__device__ __forceinline__ void ldmx4(uint32_t* r, uint32_t addr) {
    asm volatile("ldmatrix.sync.aligned.m8n8.x4.shared.b16 {%0,%1,%2,%3}, [%4];"
                 : "=r"(r[0]), "=r"(r[1]), "=r"(r[2]), "=r"(r[3]) : "r"(addr));
}

__device__ __forceinline__ void mma_f16(float* d, const uint32_t* a,
                                        uint32_t b0, uint32_t b1) {
    asm volatile(
        "mma.sync.aligned.m16n8k16.row.col.f32.f16.f16.f32 "
        "{%0,%1,%2,%3}, {%4,%5,%6,%7}, {%8,%9}, {%0,%1,%2,%3};"
        : "+f"(d[0]), "+f"(d[1]), "+f"(d[2]), "+f"(d[3])
        : "r"(a[0]), "r"(a[1]), "r"(a[2]), "r"(a[3]), "r"(b0), "r"(b1));
}

__global__ __launch_bounds__(NTHREADS, 1)
void gemm_f16_kernel(const float* __restrict__ bias, float* __restrict__ out)
{
    extern __shared__ uint4 smem[];
    const uint32_t sbase = smem_u32(smem);

    const int t    = threadIdx.x;
    const int lane = t & 31;
    const int wid  = t >> 5;           // 0..15
    const int g4   = lane >> 2;
    const int l4   = lane & 3;
    const int wm   = wid & 1;          // 0..1 (M: 64 rows each)
    const int wn   = wid >> 1;         // 0..7 (N: 32 cols each)
    const int mt   = blockIdx.y;
    const int nt   = blockIdx.x;

    // ldmatrix per-lane constants
    const int ar = lane & 7;
    const int ag = lane >> 3;
    const int rg = ag & 1;             // +8 rows
    const int cg = ag >> 1;            // +1 chunk (k+8)
    const uint32_t arow_off = (uint32_t)(wm * 64 + rg * 8 + ar) * 128u;
    const uint32_t brow_off = (uint32_t)(wn * 32 + rg * 8 + ar) * 128u;
    uint32_t sw[4];
#pragma unroll
    for (int ks = 0; ks < 4; ks++)
        sw[ks] = (uint32_t)(((ks * 2 + cg) ^ ar) * 16);

    const uint4* srcA0 = g_Xp + (size_t)mt * 64 * 1024;
    const uint4* srcB0 = g_Wp + (size_t)nt * 64 * 2048;

    float acc[4][4][4];
#pragma unroll
    for (int mf = 0; mf < 4; mf++)
#pragma unroll
        for (int nf = 0; nf < 4; nf++)
#pragma unroll
            for (int j = 0; j < 4; j++) acc[mf][nf][j] = 0.0f;

    auto load_stage = [&](int it, int s) {
        uint4* dst = smem + s * STAGE_CHUNKS;
        const uint4* sa = srcA0 + (size_t)it * 1024;
        const uint4* sb = srcB0 + (size_t)it * 2048;
        uint32_t d = smem_u32(dst);
#pragma unroll
        for (int i = 0; i < 2; i++)
            cp_async16(d + (t + i * NTHREADS) * 16, sa + t + i * NTHREADS);
        d += 1024 * 16;
#pragma unroll
        for (int i = 0; i < 4; i++)
            cp_async16(d + (t + i * NTHREADS) * 16, sb + t + i * NTHREADS);
        asm volatile("cp.async.commit_group;" ::: "memory");
    };

    load_stage(0, 0);
    load_stage(1, 1);
    load_stage(2, 2);

#pragma unroll 1
    for (int it = 0; it < NITER; ++it) {
        if (it < NITER - 2)
            asm volatile("cp.async.wait_group 2;" ::: "memory");
        else if (it == NITER - 2)
            asm volatile("cp.async.wait_group 1;" ::: "memory");
        else
            asm volatile("cp.async.wait_group 0;" ::: "memory");
        __syncthreads();

        if (it + 3 < NITER) load_stage(it + 3, (it + 3) % STAGES);

        const uint32_t aS = sbase + (uint32_t)((it % STAGES) * STAGE_CHUNKS * 16);
        const uint32_t bS = aS + 1024 * 16;

#pragma unroll
        for (int ks = 0; ks < 4; ks++) {
            uint32_t a[4][4], b[2][4];
#pragma unroll
            for (int mf = 0; mf < 4; mf++)
                ldmx4(a[mf], aS + arow_off + mf * 2048 + sw[ks]);
#pragma unroll
            for (int p = 0; p < 2; p++)
                ldmx4(b[p], bS + brow_off + p * 2048 + sw[ks]);

#pragma unroll
            for (int mf = 0; mf < 4; mf++)
#pragma unroll
                for (int p = 0; p < 2; p++) {
                    mma_f16(acc[mf][2 * p],     a[mf], b[p][0], b[p][2]);
                    mma_f16(acc[mf][2 * p + 1], a[mf], b[p][1], b[p][3]);
                }
        }
    }

    // ---- epilogue: bias add + store ----
    const int m0 = mt * BM + wm * 64;
    const int n0 = nt * BN + wn * 32;

    float2 bb[4];
#pragma unroll
    for (int nf = 0; nf < 4; nf++)
        bb[nf] = *(const float2*)(bias + n0 + nf * 8 + l4 * 2);

#pragma unroll
    for (int mf = 0; mf < 4; mf++) {
        const int m = m0 + mf * 16 + g4;
        float* r0 = out + (size_t)m * OUT_F;
        float* r1 = out + (size_t)(m + 8) * OUT_F;
#pragma unroll
        for (int nf = 0; nf < 4; nf++) {
            const int n = n0 + nf * 8 + l4 * 2;
            float2 v0, v1;
            v0.x = acc[mf][nf][0] + bb[nf].x;
            v0.y = acc[mf][nf][1] + bb[nf].y;
            v1.x = acc[mf][nf][2] + bb[nf].x;
            v1.y = acc[mf][nf][3] + bb[nf].y;
            *(float2*)(r0 + n) = v0;
            *(float2*)(r1 + n) = v1;
        }
    }
}

// ---------------------------------------------------------------------------
// Launch: x, qweight, scales, bias, lora_A, lora_B
// ---------------------------------------------------------------------------
extern "C" void kernel_launch(void* const* d_in, const int* in_sizes, int n_in,
                              void* d_out, int out_size)
{
    const float* x      = (const float*)d_in[0];
    const int*   qw     = (const int*)  d_in[1];
    const float* scales = (const float*)d_in[2];
    const float* bias   = (const float*)d_in[3];
    const float* lora_A = (const float*)d_in[4];
    const float* lora_B = (const float*)d_in[5];
    float*       out    = (float*)d_out;
    (void)in_sizes; (void)n_in; (void)out_size;

    cudaFuncSetAttribute(gemm_f16_kernel,
                         cudaFuncAttributeMaxDynamicSharedMemorySize, SMEM_BYTES);

    prep_kernel<<<2048, 256>>>(x, qw, scales, lora_A, lora_B);

    dim3 grid(OUT_F / BN, M_TOK / BM);           // (16, 16)
    gemm_f16_kernel<<<grid, NTHREADS, SMEM_BYTES>>>(bias, out);
}